// round 2
// baseline (speedup 1.0000x reference)
#include <cuda_runtime.h>
#include <stdint.h>
#include <math.h>

// Problem constants
#define NB    16
#define HW    56
#define NPIX  3136           // 56*56
#define NBP   50176          // NB*NPIX
#define C_IN  256
#define C_MID 64
#define EPSC  1e-6f
#define BNEPS 1e-5f
#define NOUT_MAIN 12845056   // 16*256*56*56

// ---------------- scratch (__device__ globals; no allocation) ----------------
__device__ float g_y  [NOUT_MAIN];   // conv output (pre-BN), per stage
__device__ float g_cos[NOUT_MAIN];   // cosine
__device__ float g_tmp[NOUT_MAIN];   // box filter horizontal pass
__device__ float g_cm [NOUT_MAIN];   // cosine_mean
__device__ float g_h  [C_MID*NBP];   // post-BN/ReLU activations (h1, then h2)
__device__ float g_ss [NBP];         // per-pixel sum of squares (or sqrt thereof)
__device__ float g_xn [NBP];         // x_norm for conv2 (sqrt of 3x3 box sum)
__device__ float g_wn [512];         // weight Frobenius norms (64 + 64 + 256)
__device__ float g_st [512];         // BN sums/sumsq interleaved
__device__ float g_acc[1];

// ---------------- threefry2x32 (JAX-exact) ----------------
__host__ __device__ __forceinline__ uint32_t rotl32(uint32_t x, int r) {
    return (x << r) | (x >> (32 - r));
}

// Reference/host version (plain rotates)
__host__ __device__ __forceinline__ void threefry2x32(
    uint32_t k0, uint32_t k1, uint32_t c0, uint32_t c1, uint32_t& o0, uint32_t& o1)
{
    uint32_t ks0 = k0, ks1 = k1, ks2 = k0 ^ k1 ^ 0x1BD11BDAu;
    uint32_t x0 = c0 + ks0, x1 = c1 + ks1;
#define TF_R(r) { x0 += x1; x1 = rotl32(x1, r); x1 ^= x0; }
    TF_R(13) TF_R(15) TF_R(26) TF_R(6)   x0 += ks1; x1 += ks2 + 1u;
    TF_R(17) TF_R(29) TF_R(16) TF_R(24)  x0 += ks2; x1 += ks0 + 2u;
    TF_R(13) TF_R(15) TF_R(26) TF_R(6)   x0 += ks0; x1 += ks1 + 3u;
    TF_R(17) TF_R(29) TF_R(16) TF_R(24)  x0 += ks1; x1 += ks2 + 4u;
    TF_R(13) TF_R(15) TF_R(26) TF_R(6)   x0 += ks2; x1 += ks0 + 5u;
#undef TF_R
    o0 = x0; o1 = x1;
}

// Device fast version: rotate via 64-bit mul (IMAD.WIDE on fma pipe) so the
// per-round alu-pipe cost is a single LOP3 ((lo|hi)^x0).
__device__ __forceinline__ void threefry2x32_dev(
    uint32_t k0, uint32_t k1, uint32_t c0, uint32_t c1, uint32_t& o0, uint32_t& o1)
{
    uint32_t ks0 = k0, ks1 = k1, ks2 = k0 ^ k1 ^ 0x1BD11BDAu;
    uint32_t x0 = c0 + ks0, x1 = c1 + ks1;
#define TF_R(r) { x0 += x1; \
    uint64_t m = (uint64_t)x1 * ((uint64_t)(1u << (r))); \
    x1 = ((uint32_t)m | (uint32_t)(m >> 32)) ^ x0; }
    TF_R(13) TF_R(15) TF_R(26) TF_R(6)   x0 += ks1; x1 += ks2 + 1u;
    TF_R(17) TF_R(29) TF_R(16) TF_R(24)  x0 += ks2; x1 += ks0 + 2u;
    TF_R(13) TF_R(15) TF_R(26) TF_R(6)   x0 += ks0; x1 += ks1 + 3u;
    TF_R(17) TF_R(29) TF_R(16) TF_R(24)  x0 += ks1; x1 += ks2 + 4u;
    TF_R(13) TF_R(15) TF_R(26) TF_R(6)   x0 += ks2; x1 += ks0 + 5u;
#undef TF_R
    o0 = x0; o1 = x1;
}

__device__ __forceinline__ float gumbel_from_bits(uint32_t bits) {
    // JAX uniform: (bits>>9 | 0x3f800000) as float - 1, then max(tiny, .)
    float u = __uint_as_float(0x3f800000u | (bits >> 9)) - 1.0f;
    u = fmaxf(u, 1.17549435e-38f);
    return -__logf(-__logf(u));
}

// ---------------- small utility kernels ----------------
__global__ void zero_acc_k() { g_acc[0] = 0.0f; }

__global__ void wnorm_k(const float* __restrict__ w, float* __restrict__ out, int len) {
    __shared__ float sm[256];
    int row = blockIdx.x;
    float s = 0.0f;
    for (int i = threadIdx.x; i < len; i += 256) {
        float v = w[(long long)row * len + i];
        s += v * v;
    }
    sm[threadIdx.x] = s; __syncthreads();
    for (int st = 128; st > 0; st >>= 1) {
        if (threadIdx.x < st) sm[threadIdx.x] += sm[threadIdx.x + st];
        __syncthreads();
    }
    if (threadIdx.x == 0) out[row] = sqrtf(sm[0]);
}

// ---------------- 1x1 conv GEMM (+optional per-pixel sumsq) ----------------
// Block: 64 out-channels x 128 pixels.  Grid: (ceil(NPIX/128), B, outC/64)
template<int CIN, bool COMPUTE_SS>
__global__ void __launch_bounds__(256) conv1x1_k(
    const float* __restrict__ X, const float* __restrict__ W,
    const float* __restrict__ wn, const float* __restrict__ xn,
    float* __restrict__ Y, float* __restrict__ COS, int outC)
{
    __shared__ float sX[16][128];
    __shared__ float sW[64][17];
    __shared__ float sF[128];
    __shared__ float sWF[64];

    const int tid  = threadIdx.x;
    const int p0   = blockIdx.x * 128;
    const int b    = blockIdx.y;
    const int co0  = blockIdx.z * 64;
    const int px_l = tid & 127, kk2 = tid >> 7;
    const int co_g = tid >> 5,  px_g = tid & 31;

    const float* Xb = X + (long long)b * CIN * NPIX;

    if (!COMPUTE_SS) {
        if (tid < 128) {
            int pp = p0 + tid;
            float v = (pp < NPIX) ? xn[b * NPIX + pp] : 1.0f;
            sF[tid] = 1.0f / (v + EPSC);
        }
    }
    if (tid < 64) sWF[tid] = 1.0f / (wn[co0 + tid] + EPSC);

    float acc[8][4];
#pragma unroll
    for (int i = 0; i < 8; i++)
#pragma unroll
        for (int j = 0; j < 4; j++) acc[i][j] = 0.0f;
    float ssacc = 0.0f;

    const int p = p0 + px_l;
    const bool pOK = p < NPIX;

    for (int kc = 0; kc < CIN; kc += 16) {
        __syncthreads();
#pragma unroll
        for (int r = 0; r < 8; r++) {
            int k = kk2 + 2 * r;
            float v = pOK ? Xb[(kc + k) * NPIX + p] : 0.0f;
            sX[k][px_l] = v;
            if (COMPUTE_SS) ssacc += v * v;
        }
        {
            int co_l = tid >> 2, ci0 = (tid & 3) * 4;
            const float* wp = W + (long long)(co0 + co_l) * CIN + kc + ci0;
#pragma unroll
            for (int r = 0; r < 4; r++) sW[co_l][ci0 + r] = wp[r];
        }
        __syncthreads();
#pragma unroll
        for (int k = 0; k < 16; k++) {
            float4 xv = *reinterpret_cast<const float4*>(&sX[k][px_g * 4]);
#pragma unroll
            for (int i = 0; i < 8; i++) {
                float wv = sW[co_g * 8 + i][k];
                acc[i][0] = fmaf(wv, xv.x, acc[i][0]);
                acc[i][1] = fmaf(wv, xv.y, acc[i][1]);
                acc[i][2] = fmaf(wv, xv.z, acc[i][2]);
                acc[i][3] = fmaf(wv, xv.w, acc[i][3]);
            }
        }
    }

    if (COMPUTE_SS) {
        __syncthreads();
        if (kk2 == 0) sF[px_l] = ssacc;
        __syncthreads();
        if (kk2 == 1) sF[px_l] += ssacc;
        __syncthreads();
        if (tid < 128) sF[tid] = 1.0f / (sqrtf(sF[tid]) + EPSC);
        __syncthreads();
    } else {
        __syncthreads();
    }

#pragma unroll
    for (int i = 0; i < 8; i++) {
        int co_l = co_g * 8 + i;
        long long base = ((long long)(b * outC + co0 + co_l)) * NPIX;
        float wf = sWF[co_l];
#pragma unroll
        for (int j = 0; j < 4; j++) {
            int px = px_g * 4 + j;
            int pp = p0 + px;
            if (pp < NPIX) {
                float yv = acc[i][j];
                Y[base + pp]   = yv;
                COS[base + pp] = yv * wf * sF[px];
            }
        }
    }
}

// ---------------- 3x3 conv (64->64, pad 1) ----------------
// Block: one image row (56 px) x 64 out-channels. Grid: (56, B)
__global__ void __launch_bounds__(128) conv3x3_k(
    const float* __restrict__ Hin, const float* __restrict__ W2,
    const float* __restrict__ wn, const float* __restrict__ xnorm,
    float* __restrict__ Y, float* __restrict__ COS)
{
    __shared__ float sX[16][60];
    __shared__ float sW[48][64];
    __shared__ float sWF[64];
    __shared__ float sF[56];

    const int yy = blockIdx.x;
    const int b  = blockIdx.y;
    const int tid = threadIdx.x;
    const int cg = tid >> 3;   // 16 groups x 4 co
    const int pg = tid & 7;    // 8 groups x 7 px

    if (tid < 64) sWF[tid] = 1.0f / (wn[tid] + EPSC);
    if (tid < 56) sF[tid]  = 1.0f / (xnorm[b * NPIX + yy * HW + tid] + EPSC);

    float acc[4][7];
#pragma unroll
    for (int i = 0; i < 4; i++)
#pragma unroll
        for (int j = 0; j < 7; j++) acc[i][j] = 0.0f;

    for (int ky = 0; ky < 3; ky++) {
        int row = yy + ky - 1;
        bool rok = (unsigned)row < (unsigned)HW;
        for (int cc = 0; cc < 4; cc++) {
            int ci0 = cc * 16;
            __syncthreads();
            for (int f = tid; f < 16 * 58; f += 128) {
                int ci = f / 58, xx = f % 58;
                int col = xx - 1;
                float v = 0.0f;
                if (rok && (unsigned)col < (unsigned)HW)
                    v = Hin[((long long)(b * C_MID + ci0 + ci)) * NPIX + row * HW + col];
                sX[ci][xx] = v;
            }
            for (int f = tid; f < 16 * 3 * 64; f += 128) {
                int co = f & 63; int rest = f >> 6;
                int ci = rest / 3, kx = rest % 3;
                sW[ci * 3 + kx][co] = W2[(long long)co * 576 + (ci0 + ci) * 9 + ky * 3 + kx];
            }
            __syncthreads();
            if (!rok) continue;
#pragma unroll
            for (int ci = 0; ci < 16; ci++) {
#pragma unroll
                for (int kx = 0; kx < 3; kx++) {
                    float wv[4];
#pragma unroll
                    for (int i = 0; i < 4; i++) wv[i] = sW[ci * 3 + kx][cg * 4 + i];
#pragma unroll
                    for (int j = 0; j < 7; j++) {
                        float xv = sX[ci][pg * 7 + j + kx];
#pragma unroll
                        for (int i = 0; i < 4; i++) acc[i][j] = fmaf(wv[i], xv, acc[i][j]);
                    }
                }
            }
        }
    }

#pragma unroll
    for (int i = 0; i < 4; i++) {
        int co = cg * 4 + i;
        long long base = ((long long)(b * C_MID + co)) * NPIX + yy * HW;
        float wf = sWF[co];
#pragma unroll
        for (int j = 0; j < 7; j++) {
            int x = pg * 7 + j;
            float yv = acc[i][j];
            Y[base + x]   = yv;
            COS[base + x] = yv * wf * sF[x];
        }
    }
}

// ---------------- 11x11 separable box filter ----------------
__global__ void boxh_k(const float* __restrict__ in, float* __restrict__ out, int total) {
    int gid = blockIdx.x * 256 + threadIdx.x;
    if (gid >= total) return;
    int x = gid % HW;
    int base = gid - x;
    int lo = max(x - 5, 0), hi = min(x + 5, HW - 1);
    float s = 0.0f;
    for (int xx = lo; xx <= hi; xx++) s += in[base + xx];
    out[gid] = s;
}

__global__ void boxv_k(const float* __restrict__ in, float* __restrict__ out, int total) {
    int gid = blockIdx.x * 256 + threadIdx.x;
    if (gid >= total) return;
    int p = gid % NPIX;
    int x = p % HW, y = p / HW;
    int base = gid - p + x;
    int lo = max(y - 5, 0), hi = min(y + 5, HW - 1);
    float s = 0.0f;
    for (int yy = lo; yy <= hi; yy++) s += in[base + yy * HW];
    out[gid] = s * (1.0f / 121.0f);
}

// ---------------- 3x3 box sum of ss -> sqrt (x_norm for conv2) ----------------
__global__ void box3_k(const float* __restrict__ ss, float* __restrict__ xn) {
    int gid = blockIdx.x * 256 + threadIdx.x;
    if (gid >= NBP) return;
    int b = gid / NPIX, p = gid % NPIX;
    int y = p / HW, x = p % HW;
    float s = 0.0f;
    for (int dy = -1; dy <= 1; dy++) {
        int yy = y + dy;
        if ((unsigned)yy >= (unsigned)HW) continue;
        for (int dx = -1; dx <= 1; dx++) {
            int xx = x + dx;
            if ((unsigned)xx >= (unsigned)HW) continue;
            s += ss[b * NPIX + yy * HW + xx];
        }
    }
    xn[gid] = sqrtf(s);
}

// ---------------- Gumbel-argmax sampling (partitionable threefry) ------------
// JAX threefry_partitionable: element e gets counter (hi(e)=0, lo(e)=e),
// bits = o0 ^ o1. One warp per (s,b,c) unit; argmax over 3136 positions.
__global__ void sample_k(const float* __restrict__ cosb, const float* __restrict__ cmb,
                         int C, uint32_t k0, uint32_t k1, int units, float scale)
{
    int wid  = (blockIdx.x * blockDim.x + threadIdx.x) >> 5;
    int lane = threadIdx.x & 31;
    if (wid >= units) return;
    int c = wid % C, b = (wid / C) % NB;
    const float* lrow = cosb + (long long)(b * C + c) * NPIX;
    uint32_t ebase = (uint32_t)wid * NPIX;

    float bv = -1e30f;
    int bi = 0;
    for (int p = lane; p < NPIX; p += 32) {
        uint32_t o0, o1;
        threefry2x32_dev(k0, k1, 0u, ebase + (uint32_t)p, o0, o1);
        float v = fmaf(lrow[p], 2.0f, gumbel_from_bits(o0 ^ o1));  // logits = cos/0.5
        if (v > bv) { bv = v; bi = p; }
    }
#pragma unroll
    for (int off = 16; off; off >>= 1) {
        float ov = __shfl_xor_sync(0xffffffffu, bv, off);
        int   oi = __shfl_xor_sync(0xffffffffu, bi, off);
        if (ov > bv || (ov == bv && oi < bi)) { bv = ov; bi = oi; }
    }
    if (lane == 0) {
        float v = cmb[(long long)(b * C + c) * NPIX + bi];
        atomicAdd(&g_acc[0], v * scale);
    }
}

// ---------------- BatchNorm: stats then apply(+relu, + per-pixel sumsq) ------
__global__ void bnstats_k(const float* __restrict__ Y, float* __restrict__ st, int C) {
    __shared__ float r1[256], r2[256];
    int c = blockIdx.x;
    float s = 0.0f, s2 = 0.0f;
    for (int i = threadIdx.x; i < NBP; i += 256) {
        int b = i / NPIX, p = i - b * NPIX;
        float v = Y[((long long)(b * C + c)) * NPIX + p];
        s += v; s2 += v * v;
    }
    r1[threadIdx.x] = s; r2[threadIdx.x] = s2; __syncthreads();
    for (int stp = 128; stp > 0; stp >>= 1) {
        if (threadIdx.x < stp) { r1[threadIdx.x] += r1[threadIdx.x + stp];
                                 r2[threadIdx.x] += r2[threadIdx.x + stp]; }
        __syncthreads();
    }
    if (threadIdx.x == 0) { st[2 * c] = r1[0]; st[2 * c + 1] = r2[0]; }
}

template<bool SQRT_SS>
__global__ void bnapply_k(const float* __restrict__ Y,
                          const float* __restrict__ gam, const float* __restrict__ bet,
                          const float* __restrict__ st,
                          float* __restrict__ Hout, float* __restrict__ ssout)
{
    __shared__ float sc[C_MID], sh[C_MID];
    if (threadIdx.x < C_MID) {
        int c = threadIdx.x;
        float m = st[2 * c] / (float)NBP;
        float v = st[2 * c + 1] / (float)NBP - m * m;
        float is = rsqrtf(v + BNEPS);
        sc[c] = gam[c] * is;
        sh[c] = bet[c] - m * gam[c] * is;
    }
    __syncthreads();
    int gid = blockIdx.x * 256 + threadIdx.x;
    if (gid >= NBP) return;
    int b = gid / NPIX, p = gid - b * NPIX;
    long long base = (long long)b * C_MID * NPIX + p;
    float ss = 0.0f;
    for (int c = 0; c < C_MID; c++) {
        float v = Y[base + c * NPIX];
        float h = fmaxf(fmaf(v, sc[c], sh[c]), 0.0f);
        Hout[base + c * NPIX] = h;
        ss += h * h;
    }
    ssout[gid] = SQRT_SS ? sqrtf(ss) : ss;
}

// ---------------- Final: BN3 + residual + ReLU ----------------
__global__ void final_k(const float* __restrict__ Y, const float* __restrict__ X,
                        const float* __restrict__ gam, const float* __restrict__ bet,
                        const float* __restrict__ st, float* __restrict__ out)
{
    __shared__ float sc[C_IN], sh[C_IN];
    {
        int c = threadIdx.x;
        float m = st[2 * c] / (float)NBP;
        float v = st[2 * c + 1] / (float)NBP - m * m;
        float is = rsqrtf(v + BNEPS);
        sc[c] = gam[c] * is;
        sh[c] = bet[c] - m * gam[c] * is;
    }
    __syncthreads();
    int gid = blockIdx.x * 256 + threadIdx.x;
    int c = (gid / NPIX) & 255;
    out[gid] = fmaxf(fmaf(Y[gid], sc[c], sh[c]) + X[gid], 0.0f);
}

__global__ void writeacc_k(float* out) { out[NOUT_MAIN] = g_acc[0]; }

// ---------------- host ----------------
static void host_keys(uint32_t* K) {
    // Partitionable (foldlike) split of key(42) = (0, 42):
    //   subkey_i = threefry((0,42), c0=0, c1=i)  -> key data (o0, o1)
    threefry2x32(0u, 42u, 0u, 0u, K[0], K[1]);   // k0
    threefry2x32(0u, 42u, 0u, 1u, K[2], K[3]);   // k1
    threefry2x32(0u, 42u, 0u, 2u, K[4], K[5]);   // k2
}

extern "C" void kernel_launch(void* const* d_in, const int* in_sizes, int n_in,
                              void* d_out, int out_size)
{
    const float* x  = (const float*)d_in[0];
    const float* w1 = (const float*)d_in[1];
    const float* w2 = (const float*)d_in[2];
    const float* w3 = (const float*)d_in[3];
    const float* g1 = (const float*)d_in[4];
    const float* b1 = (const float*)d_in[5];
    const float* g2 = (const float*)d_in[6];
    const float* b2 = (const float*)d_in[7];
    const float* g3 = (const float*)d_in[8];
    const float* b3 = (const float*)d_in[9];
    float* out = (float*)d_out;

    float *yP, *cosP, *tmpP, *cmP, *hP, *ssP, *xnP, *wnP, *stP;
    cudaGetSymbolAddress((void**)&yP,   g_y);
    cudaGetSymbolAddress((void**)&cosP, g_cos);
    cudaGetSymbolAddress((void**)&tmpP, g_tmp);
    cudaGetSymbolAddress((void**)&cmP,  g_cm);
    cudaGetSymbolAddress((void**)&hP,   g_h);
    cudaGetSymbolAddress((void**)&ssP,  g_ss);
    cudaGetSymbolAddress((void**)&xnP,  g_xn);
    cudaGetSymbolAddress((void**)&wnP,  g_wn);
    cudaGetSymbolAddress((void**)&stP,  g_st);

    uint32_t K[6]; host_keys(K);

    const int n64 = C_MID * NBP;           // 3,211,264
    const int n256 = NOUT_MAIN;            // 12,845,056

    zero_acc_k<<<1, 32>>>();
    wnorm_k<<<64, 256>>>(w1, wnP, 256);
    wnorm_k<<<64, 256>>>(w2, wnP + 64, 576);
    wnorm_k<<<256, 256>>>(w3, wnP + 128, 64);

    // ---- stage 1: conv1 1x1 (256->64) ----
    conv1x1_k<C_IN, true><<<dim3(25, NB, 1), 256>>>(x, w1, wnP, nullptr, yP, cosP, C_MID);
    boxh_k<<<(n64 + 255) / 256, 256>>>(cosP, tmpP, n64);
    boxv_k<<<(n64 + 255) / 256, 256>>>(tmpP, cmP, n64);
    sample_k<<<(5120 * 32) / 256, 256>>>(cosP, cmP, C_MID, K[0], K[1], 5120, 1.0f / 5120.0f);
    bnstats_k<<<C_MID, 256>>>(yP, stP, C_MID);
    bnapply_k<false><<<196, 256>>>(yP, g1, b1, stP, hP, ssP);
    box3_k<<<196, 256>>>(ssP, xnP);

    // ---- stage 2: conv2 3x3 (64->64) ----
    conv3x3_k<<<dim3(HW, NB), 128>>>(hP, w2, wnP + 64, xnP, yP, cosP);
    boxh_k<<<(n64 + 255) / 256, 256>>>(cosP, tmpP, n64);
    boxv_k<<<(n64 + 255) / 256, 256>>>(tmpP, cmP, n64);
    sample_k<<<(5120 * 32) / 256, 256>>>(cosP, cmP, C_MID, K[2], K[3], 5120, 1.0f / 5120.0f);
    bnstats_k<<<C_MID, 256>>>(yP, stP, C_MID);
    bnapply_k<true><<<196, 256>>>(yP, g2, b2, stP, hP, ssP);  // ssP <- sqrt(sum h^2)

    // ---- stage 3: conv3 1x1 (64->256) ----
    conv1x1_k<C_MID, false><<<dim3(25, NB, 4), 256>>>(hP, w3, wnP + 128, ssP, yP, cosP, C_IN);
    boxh_k<<<(n256 + 255) / 256, 256>>>(cosP, tmpP, n256);
    boxv_k<<<(n256 + 255) / 256, 256>>>(tmpP, cmP, n256);
    sample_k<<<(20480 * 32) / 256, 256>>>(cosP, cmP, C_IN, K[4], K[5], 20480, 1.0f / 20480.0f);
    bnstats_k<<<C_IN, 256>>>(yP, stP, C_IN);
    final_k<<<n256 / 256, 256>>>(yP, x, g3, b3, stP, out);
    if (out_size > NOUT_MAIN) writeacc_k<<<1, 1>>>(out);
}

// round 3
// speedup vs baseline: 1.2560x; 1.2560x over previous
#include <cuda_runtime.h>
#include <stdint.h>
#include <math.h>

// Problem constants
#define NB    16
#define HW    56
#define NPIX  3136           // 56*56
#define NBP   50176          // NB*NPIX
#define C_IN  256
#define C_MID 64
#define EPSC  1e-6f
#define BNEPS 1e-5f
#define NOUT_MAIN 12845056   // 16*256*56*56

// ---------------- scratch (__device__ globals; no allocation) ----------------
__device__ float g_y  [NOUT_MAIN];   // conv output (pre-BN), per stage
__device__ float g_cos[NOUT_MAIN];   // cosine
__device__ float g_h  [C_MID*NBP];   // post-BN/ReLU activations (h1, then h2)
__device__ float g_ss [NBP];         // per-pixel sum of squares (or sqrt thereof)
__device__ float g_xn [NBP];         // x_norm for conv2 (sqrt of 3x3 box sum)
__device__ float g_wn [512];         // weight Frobenius norms (64 + 64 + 256)
__device__ float g_st [768];         // BN sums/sumsq: stage1 [0,128) stage2 [128,256) stage3 [256,768)
__device__ float g_acc[1];

// ---------------- f32x2 packed math ----------------
__device__ __forceinline__ void ffma2(uint64_t& d, uint64_t a, uint64_t b) {
    asm("fma.rn.f32x2 %0, %1, %2, %0;" : "+l"(d) : "l"(a), "l"(b));
}
__device__ __forceinline__ uint64_t bcast2(float w) {
    uint64_t r; asm("mov.b64 %0, {%1, %1};" : "=l"(r) : "f"(w)); return r;
}
__device__ __forceinline__ void unpack2(uint64_t v, float& lo, float& hi) {
    asm("mov.b64 {%0, %1}, %2;" : "=f"(lo), "=f"(hi) : "l"(v));
}

// ---------------- threefry2x32 (JAX-exact, partitionable mode) ----------------
__host__ __device__ __forceinline__ uint32_t rotl32(uint32_t x, int r) {
    return (x << r) | (x >> (32 - r));
}

__host__ __device__ __forceinline__ void threefry2x32(
    uint32_t k0, uint32_t k1, uint32_t c0, uint32_t c1, uint32_t& o0, uint32_t& o1)
{
    uint32_t ks0 = k0, ks1 = k1, ks2 = k0 ^ k1 ^ 0x1BD11BDAu;
    uint32_t x0 = c0 + ks0, x1 = c1 + ks1;
#define TF_R(r) { x0 += x1; x1 = rotl32(x1, r); x1 ^= x0; }
    TF_R(13) TF_R(15) TF_R(26) TF_R(6)   x0 += ks1; x1 += ks2 + 1u;
    TF_R(17) TF_R(29) TF_R(16) TF_R(24)  x0 += ks2; x1 += ks0 + 2u;
    TF_R(13) TF_R(15) TF_R(26) TF_R(6)   x0 += ks0; x1 += ks1 + 3u;
    TF_R(17) TF_R(29) TF_R(16) TF_R(24)  x0 += ks1; x1 += ks2 + 4u;
    TF_R(13) TF_R(15) TF_R(26) TF_R(6)   x0 += ks2; x1 += ks0 + 5u;
#undef TF_R
    o0 = x0; o1 = x1;
}

// Device version: rotate via widening mul (fma pipe) -> round = add + IMAD.WIDE + LOP3.
__device__ __forceinline__ void threefry2x32_dev(
    uint32_t k0, uint32_t k1, uint32_t c0, uint32_t c1, uint32_t& o0, uint32_t& o1)
{
    uint32_t ks0 = k0, ks1 = k1, ks2 = k0 ^ k1 ^ 0x1BD11BDAu;
    uint32_t x0 = c0 + ks0, x1 = c1 + ks1;
#define TF_R(r) { x0 += x1; \
    uint64_t m = (uint64_t)x1 * ((uint64_t)(1u << (r))); \
    x1 = ((uint32_t)m | (uint32_t)(m >> 32)) ^ x0; }
    TF_R(13) TF_R(15) TF_R(26) TF_R(6)   x0 += ks1; x1 += ks2 + 1u;
    TF_R(17) TF_R(29) TF_R(16) TF_R(24)  x0 += ks2; x1 += ks0 + 2u;
    TF_R(13) TF_R(15) TF_R(26) TF_R(6)   x0 += ks0; x1 += ks1 + 3u;
    TF_R(17) TF_R(29) TF_R(16) TF_R(24)  x0 += ks1; x1 += ks2 + 4u;
    TF_R(13) TF_R(15) TF_R(26) TF_R(6)   x0 += ks2; x1 += ks0 + 5u;
#undef TF_R
    o0 = x0; o1 = x1;
}

__device__ __forceinline__ float gumbel_from_bits(uint32_t bits) {
    float u = __uint_as_float(0x3f800000u | (bits >> 9)) - 1.0f;
    u = fmaxf(u, 1.17549435e-38f);
    return -__logf(-__logf(u));
}

// ---------------- init: zero acc + BN stat accumulators ----------------
__global__ void zero_k() {
    int t = threadIdx.x;
    for (int i = t; i < 768; i += 256) g_st[i] = 0.0f;
    if (t == 0) g_acc[0] = 0.0f;
}

__global__ void wnorm_k(const float* __restrict__ w, float* __restrict__ out, int len) {
    __shared__ float sm[256];
    int row = blockIdx.x;
    float s = 0.0f;
    for (int i = threadIdx.x; i < len; i += 256) {
        float v = w[(long long)row * len + i];
        s += v * v;
    }
    sm[threadIdx.x] = s; __syncthreads();
    for (int st = 128; st > 0; st >>= 1) {
        if (threadIdx.x < st) sm[threadIdx.x] += sm[threadIdx.x + st];
        __syncthreads();
    }
    if (threadIdx.x == 0) out[row] = sqrtf(sm[0]);
}

// ---------------- 1x1 conv GEMM (f32x2) + cosine + fused BN stats ------------
// Block: 64 out-channels x 128 pixels.  Grid: (25, B, outC/64)
template<int CIN, bool COMPUTE_SS>
__global__ void __launch_bounds__(256) conv1x1_k(
    const float* __restrict__ X, const float* __restrict__ W,
    const float* __restrict__ wn, const float* __restrict__ xn,
    float* __restrict__ Y, float* __restrict__ COS,
    float* __restrict__ stbase, int outC)
{
    __shared__ float sX[16][128];
    __shared__ float sW[64][17];
    __shared__ float sF[128];
    __shared__ float sWF[64];

    const int tid  = threadIdx.x;
    const int p0   = blockIdx.x * 128;
    const int b    = blockIdx.y;
    const int co0  = blockIdx.z * 64;
    const int px_l = tid & 127, kk2 = tid >> 7;
    const int co_g = tid >> 5,  px_g = tid & 31;

    const float* Xb = X + (long long)b * CIN * NPIX;

    if (!COMPUTE_SS) {
        if (tid < 128) {
            int pp = p0 + tid;
            float v = (pp < NPIX) ? xn[b * NPIX + pp] : 1.0f;
            sF[tid] = 1.0f / (v + EPSC);
        }
    }
    if (tid < 64) sWF[tid] = 1.0f / (wn[co0 + tid] + EPSC);

    uint64_t acc2[8][2];
#pragma unroll
    for (int i = 0; i < 8; i++) { acc2[i][0] = 0ull; acc2[i][1] = 0ull; }
    float ssacc = 0.0f;

    const int p = p0 + px_l;
    const bool pOK = p < NPIX;

    for (int kc = 0; kc < CIN; kc += 16) {
        __syncthreads();
#pragma unroll
        for (int r = 0; r < 8; r++) {
            int k = kk2 + 2 * r;
            float v = pOK ? Xb[(kc + k) * NPIX + p] : 0.0f;
            sX[k][px_l] = v;
            if (COMPUTE_SS) ssacc += v * v;
        }
        {
            int co_l = tid >> 2, ci0 = (tid & 3) * 4;
            const float* wp = W + (long long)(co0 + co_l) * CIN + kc + ci0;
#pragma unroll
            for (int r = 0; r < 4; r++) sW[co_l][ci0 + r] = wp[r];
        }
        __syncthreads();
#pragma unroll
        for (int k = 0; k < 16; k++) {
            const ulonglong2 xv = *reinterpret_cast<const ulonglong2*>(&sX[k][px_g * 4]);
#pragma unroll
            for (int i = 0; i < 8; i++) {
                uint64_t wv = bcast2(sW[co_g * 8 + i][k]);
                ffma2(acc2[i][0], wv, xv.x);
                ffma2(acc2[i][1], wv, xv.y);
            }
        }
    }

    if (COMPUTE_SS) {
        __syncthreads();
        if (kk2 == 0) sF[px_l] = ssacc;
        __syncthreads();
        if (kk2 == 1) sF[px_l] += ssacc;
        __syncthreads();
        if (tid < 128) sF[tid] = 1.0f / (sqrtf(sF[tid]) + EPSC);
        __syncthreads();
    } else {
        __syncthreads();
    }

    float s1[8], s2[8];
#pragma unroll
    for (int i = 0; i < 8; i++) {
        int co_l = co_g * 8 + i;
        long long base = ((long long)(b * outC + co0 + co_l)) * NPIX;
        float wf = sWF[co_l];
        float yv[4];
        unpack2(acc2[i][0], yv[0], yv[1]);
        unpack2(acc2[i][1], yv[2], yv[3]);
        float a = 0.0f, a2 = 0.0f;
#pragma unroll
        for (int j = 0; j < 4; j++) {
            int px = px_g * 4 + j;
            int pp = p0 + px;
            if (pp < NPIX) {
                Y[base + pp]   = yv[j];
                COS[base + pp] = yv[j] * wf * sF[px];
                a += yv[j]; a2 += yv[j] * yv[j];
            }
        }
        s1[i] = a; s2[i] = a2;
    }
    // warp shuffle-reduce over 32 px lanes (same co set per warp), then atomics
#pragma unroll
    for (int i = 0; i < 8; i++) {
#pragma unroll
        for (int off = 16; off; off >>= 1) {
            s1[i] += __shfl_xor_sync(0xffffffffu, s1[i], off);
            s2[i] += __shfl_xor_sync(0xffffffffu, s2[i], off);
        }
    }
    if (px_g == 0) {
#pragma unroll
        for (int i = 0; i < 8; i++) {
            int c = co0 + co_g * 8 + i;
            atomicAdd(&stbase[2 * c],     s1[i]);
            atomicAdd(&stbase[2 * c + 1], s2[i]);
        }
    }
}

// ---------------- 3x3 conv (64->64, pad 1) + cosine + fused BN stats ---------
// Block: one image row (56 px) x 64 out-channels. Grid: (56, B)
__global__ void __launch_bounds__(128) conv3x3_k(
    const float* __restrict__ Hin, const float* __restrict__ W2,
    const float* __restrict__ wn, const float* __restrict__ xnorm,
    float* __restrict__ Y, float* __restrict__ COS, float* __restrict__ stbase)
{
    __shared__ float sX[16][60];
    __shared__ float sW[48][64];
    __shared__ float sWF[64];
    __shared__ float sF[56];

    const int yy = blockIdx.x;
    const int b  = blockIdx.y;
    const int tid = threadIdx.x;
    const int cg = tid >> 3;   // 16 groups x 4 co
    const int pg = tid & 7;    // 8 groups x 7 px

    if (tid < 64) sWF[tid] = 1.0f / (wn[tid] + EPSC);
    if (tid < 56) sF[tid]  = 1.0f / (xnorm[b * NPIX + yy * HW + tid] + EPSC);

    float acc[4][7];
#pragma unroll
    for (int i = 0; i < 4; i++)
#pragma unroll
        for (int j = 0; j < 7; j++) acc[i][j] = 0.0f;

    for (int ky = 0; ky < 3; ky++) {
        int row = yy + ky - 1;
        bool rok = (unsigned)row < (unsigned)HW;
        for (int cc = 0; cc < 4; cc++) {
            int ci0 = cc * 16;
            __syncthreads();
            for (int f = tid; f < 16 * 58; f += 128) {
                int ci = f / 58, xx = f % 58;
                int col = xx - 1;
                float v = 0.0f;
                if (rok && (unsigned)col < (unsigned)HW)
                    v = Hin[((long long)(b * C_MID + ci0 + ci)) * NPIX + row * HW + col];
                sX[ci][xx] = v;
            }
            for (int f = tid; f < 16 * 3 * 64; f += 128) {
                int co = f & 63; int rest = f >> 6;
                int ci = rest / 3, kx = rest % 3;
                sW[ci * 3 + kx][co] = W2[(long long)co * 576 + (ci0 + ci) * 9 + ky * 3 + kx];
            }
            __syncthreads();
            if (!rok) continue;
#pragma unroll
            for (int ci = 0; ci < 16; ci++) {
#pragma unroll
                for (int kx = 0; kx < 3; kx++) {
                    float wv[4];
#pragma unroll
                    for (int i = 0; i < 4; i++) wv[i] = sW[ci * 3 + kx][cg * 4 + i];
#pragma unroll
                    for (int j = 0; j < 7; j++) {
                        float xv = sX[ci][pg * 7 + j + kx];
#pragma unroll
                        for (int i = 0; i < 4; i++) acc[i][j] = fmaf(wv[i], xv, acc[i][j]);
                    }
                }
            }
        }
    }

    float s1[4], s2[4];
#pragma unroll
    for (int i = 0; i < 4; i++) {
        int co = cg * 4 + i;
        long long base = ((long long)(b * C_MID + co)) * NPIX + yy * HW;
        float wf = sWF[co];
        float a = 0.0f, a2 = 0.0f;
#pragma unroll
        for (int j = 0; j < 7; j++) {
            int x = pg * 7 + j;
            float yv = acc[i][j];
            Y[base + x]   = yv;
            COS[base + x] = yv * wf * sF[x];
            a += yv; a2 += yv * yv;
        }
        s1[i] = a; s2[i] = a2;
    }
    // reduce over the 8 pg lanes (low 3 lane bits), then atomics
#pragma unroll
    for (int i = 0; i < 4; i++) {
#pragma unroll
        for (int off = 4; off; off >>= 1) {
            s1[i] += __shfl_xor_sync(0xffffffffu, s1[i], off);
            s2[i] += __shfl_xor_sync(0xffffffffu, s2[i], off);
        }
    }
    if (pg == 0) {
#pragma unroll
        for (int i = 0; i < 4; i++) {
            int c = cg * 4 + i;
            atomicAdd(&stbase[2 * c],     s1[i]);
            atomicAdd(&stbase[2 * c + 1], s2[i]);
        }
    }
}

// ---------------- 3x3 box sum of ss -> sqrt (x_norm for conv2) ----------------
__global__ void box3_k(const float* __restrict__ ss, float* __restrict__ xn) {
    int gid = blockIdx.x * 256 + threadIdx.x;
    if (gid >= NBP) return;
    int b = gid / NPIX, p = gid % NPIX;
    int y = p / HW, x = p % HW;
    float s = 0.0f;
    for (int dy = -1; dy <= 1; dy++) {
        int yy = y + dy;
        if ((unsigned)yy >= (unsigned)HW) continue;
        for (int dx = -1; dx <= 1; dx++) {
            int xx = x + dx;
            if ((unsigned)xx >= (unsigned)HW) continue;
            s += ss[b * NPIX + yy * HW + xx];
        }
    }
    xn[gid] = sqrtf(s);
}

// ---------------- Gumbel-argmax sampling + on-the-fly 11x11 mean -------------
// One warp per (s,b,c) unit. After argmax, the warp computes the 11x11 box
// mean of cosine at the winner directly (121 taps) -- no cosine_mean pass.
__global__ void sample_k(const float* __restrict__ cosb,
                         int C, uint32_t k0, uint32_t k1, int units, float scale)
{
    int wid  = (blockIdx.x * blockDim.x + threadIdx.x) >> 5;
    int lane = threadIdx.x & 31;
    if (wid >= units) return;
    int c = wid % C, b = (wid / C) % NB;
    const float* plane = cosb + (long long)(b * C + c) * NPIX;
    uint32_t ebase = (uint32_t)wid * NPIX;

    float bv = -1e30f;
    int bi = 0;
    for (int p = lane; p < NPIX; p += 32) {
        uint32_t o0, o1;
        threefry2x32_dev(k0, k1, 0u, ebase + (uint32_t)p, o0, o1);
        float v = fmaf(plane[p], 2.0f, gumbel_from_bits(o0 ^ o1));  // logits = cos/0.5
        if (v > bv) { bv = v; bi = p; }
    }
#pragma unroll
    for (int off = 16; off; off >>= 1) {
        float ov = __shfl_xor_sync(0xffffffffu, bv, off);
        int   oi = __shfl_xor_sync(0xffffffffu, bi, off);
        if (ov > bv || (ov == bv && oi < bi)) { bv = ov; bi = oi; }
    }
    // all lanes now agree on bi; compute 11x11 box sum at winner
    int wy = bi / HW, wx = bi - wy * HW;
    float s = 0.0f;
    for (int t = lane; t < 121; t += 32) {
        int dy = t / 11 - 5, dx = t - (t / 11) * 11 - 5;
        int yy = wy + dy, xx = wx + dx;
        if ((unsigned)yy < (unsigned)HW && (unsigned)xx < (unsigned)HW)
            s += plane[yy * HW + xx];
    }
#pragma unroll
    for (int off = 16; off; off >>= 1) s += __shfl_xor_sync(0xffffffffu, s, off);
    if (lane == 0) atomicAdd(&g_acc[0], s * scale);
}

// ---------------- BN apply (+relu, + per-pixel sumsq) ------------------------
template<bool SQRT_SS>
__global__ void bnapply_k(const float* __restrict__ Y,
                          const float* __restrict__ gam, const float* __restrict__ bet,
                          const float* __restrict__ st,
                          float* __restrict__ Hout, float* __restrict__ ssout)
{
    __shared__ float sc[C_MID], sh[C_MID];
    if (threadIdx.x < C_MID) {
        int c = threadIdx.x;
        float m = st[2 * c] / (float)NBP;
        float v = st[2 * c + 1] / (float)NBP - m * m;
        float is = rsqrtf(v + BNEPS);
        sc[c] = gam[c] * is;
        sh[c] = bet[c] - m * gam[c] * is;
    }
    __syncthreads();
    int gid = blockIdx.x * 256 + threadIdx.x;
    if (gid >= NBP) return;
    int b = gid / NPIX, p = gid - b * NPIX;
    long long base = (long long)b * C_MID * NPIX + p;
    float ss = 0.0f;
    for (int c = 0; c < C_MID; c++) {
        float v = Y[base + c * NPIX];
        float h = fmaxf(fmaf(v, sc[c], sh[c]), 0.0f);
        Hout[base + c * NPIX] = h;
        ss += h * h;
    }
    ssout[gid] = SQRT_SS ? sqrtf(ss) : ss;
}

// ---------------- Final: BN3 + residual + ReLU ----------------
__global__ void final_k(const float* __restrict__ Y, const float* __restrict__ X,
                        const float* __restrict__ gam, const float* __restrict__ bet,
                        const float* __restrict__ st, float* __restrict__ out)
{
    __shared__ float sc[C_IN], sh[C_IN];
    {
        int c = threadIdx.x;
        float m = st[2 * c] / (float)NBP;
        float v = st[2 * c + 1] / (float)NBP - m * m;
        float is = rsqrtf(v + BNEPS);
        sc[c] = gam[c] * is;
        sh[c] = bet[c] - m * gam[c] * is;
    }
    __syncthreads();
    int gid = blockIdx.x * 256 + threadIdx.x;
    int c = (gid / NPIX) & 255;
    out[gid] = fmaxf(fmaf(Y[gid], sc[c], sh[c]) + X[gid], 0.0f);
}

__global__ void writeacc_k(float* out) { out[NOUT_MAIN] = g_acc[0]; }

// ---------------- host ----------------
static void host_keys(uint32_t* K) {
    // Partitionable (foldlike) split of key(42) = (0, 42)
    threefry2x32(0u, 42u, 0u, 0u, K[0], K[1]);   // k0
    threefry2x32(0u, 42u, 0u, 1u, K[2], K[3]);   // k1
    threefry2x32(0u, 42u, 0u, 2u, K[4], K[5]);   // k2
}

extern "C" void kernel_launch(void* const* d_in, const int* in_sizes, int n_in,
                              void* d_out, int out_size)
{
    const float* x  = (const float*)d_in[0];
    const float* w1 = (const float*)d_in[1];
    const float* w2 = (const float*)d_in[2];
    const float* w3 = (const float*)d_in[3];
    const float* g1 = (const float*)d_in[4];
    const float* b1 = (const float*)d_in[5];
    const float* g2 = (const float*)d_in[6];
    const float* b2 = (const float*)d_in[7];
    const float* g3 = (const float*)d_in[8];
    const float* b3 = (const float*)d_in[9];
    float* out = (float*)d_out;

    float *yP, *cosP, *hP, *ssP, *xnP, *wnP, *stP;
    cudaGetSymbolAddress((void**)&yP,   g_y);
    cudaGetSymbolAddress((void**)&cosP, g_cos);
    cudaGetSymbolAddress((void**)&hP,   g_h);
    cudaGetSymbolAddress((void**)&ssP,  g_ss);
    cudaGetSymbolAddress((void**)&xnP,  g_xn);
    cudaGetSymbolAddress((void**)&wnP,  g_wn);
    cudaGetSymbolAddress((void**)&stP,  g_st);

    uint32_t K[6]; host_keys(K);

    zero_k<<<1, 256>>>();
    wnorm_k<<<64, 256>>>(w1, wnP, 256);
    wnorm_k<<<64, 256>>>(w2, wnP + 64, 576);
    wnorm_k<<<256, 256>>>(w3, wnP + 128, 64);

    // ---- stage 1: conv1 1x1 (256->64) ----
    conv1x1_k<C_IN, true><<<dim3(25, NB, 1), 256>>>(x, w1, wnP, nullptr, yP, cosP, stP, C_MID);
    bnapply_k<false><<<196, 256>>>(yP, g1, b1, stP, hP, ssP);
    box3_k<<<196, 256>>>(ssP, xnP);
    sample_k<<<640, 256>>>(cosP, C_MID, K[0], K[1], 5120, 1.0f / (5120.0f * 121.0f));

    // ---- stage 2: conv2 3x3 (64->64) ----
    conv3x3_k<<<dim3(HW, NB), 128>>>(hP, w2, wnP + 64, xnP, yP, cosP, stP + 128);
    bnapply_k<true><<<196, 256>>>(yP, g2, b2, stP + 128, hP, ssP);  // ssP <- sqrt(sum h^2)
    sample_k<<<640, 256>>>(cosP, C_MID, K[2], K[3], 5120, 1.0f / (5120.0f * 121.0f));

    // ---- stage 3: conv3 1x1 (64->256) ----
    conv1x1_k<C_MID, false><<<dim3(25, NB, 4), 256>>>(hP, w3, wnP + 128, ssP, yP, cosP, stP + 256, C_IN);
    sample_k<<<2560, 256>>>(cosP, C_IN, K[4], K[5], 20480, 1.0f / (20480.0f * 121.0f));
    final_k<<<NOUT_MAIN / 256, 256>>>(yP, x, g3, b3, stP + 256, out);
    if (out_size > NOUT_MAIN) writeacc_k<<<1, 1>>>(out);
}